// round 2
// baseline (speedup 1.0000x reference)
#include <cuda_runtime.h>

// Problem constants
#define S    8192
#define D    768
#define D4   (D/4)        // 192 float4 per row
#define NA   256
#define NO   256
#define NP   (NA*NO)      // 65536 pairs
#define MAXW 40
#define NCAT 13
#define NPOL 3
#define NK   18           // 2 valid + 13 cat + 3 pol partials per span

// Output layout (flattened tuple, fp32):
//   [0)                 pair_reps  NP*2D
//   [OFF_AID)           asp_ids    NP
//   [OFF_OID)           opi_ids    NP
//   [OFF_CAT)           cate_out   NP*NCAT
//   [OFF_POL)           polar_out  NP*NPOL
//   [OFF_MSK)           valid_mask NP
#define OFF_AID ((size_t)NP * (2*D))
#define OFF_OID (OFF_AID + NP)
#define OFF_CAT (OFF_OID + NP)
#define OFF_POL (OFF_CAT + (size_t)NP*NCAT)
#define OFF_MSK (OFF_POL + (size_t)NP*NPOL)

// Scratch (allocation-free rule: device globals)
__device__ float g_rep[(NA+NO)*D];     // aspect rows [0,256), opinion rows [256,512)
__device__ float g_part[(NA+NO)*NK];   // per-span partial logits (18 each)

// ---------------------------------------------------------------------------
// Kernel A: span max-pool. One block per span (512 blocks, 192 threads = 1
// float4 lane per thread). Fully coalesced word_rep reads.
// ---------------------------------------------------------------------------
__global__ void __launch_bounds__(192) span_pool_kernel(
    const float* __restrict__ word_rep,
    const int*   __restrict__ aspects,
    const int*   __restrict__ opinions)
{
    int s = blockIdx.x;                       // 0..511
    const int* sp = (s < NA) ? (aspects + 2*s) : (opinions + 2*(s - NA));
    int head = sp[0];
    int w    = sp[1] - head;                  // 1..40, head+w <= S
    int c = threadIdx.x;                      // float4 lane 0..191

    const float4* wr = (const float4*)word_rep;
    float4 m = wr[(size_t)head * D4 + c];
    for (int k = 1; k < w; ++k) {
        float4 v = wr[(size_t)(head + k) * D4 + c];
        m.x = fmaxf(m.x, v.x);
        m.y = fmaxf(m.y, v.y);
        m.z = fmaxf(m.z, v.z);
        m.w = fmaxf(m.w, v.w);
    }
    ((float4*)g_rep)[(size_t)s * D4 + c] = m;
}

// ---------------------------------------------------------------------------
// Kernel B: per-span partial logits. logit(pair i,j) splits as
//   asp_rep[i] . W[0:768]  +  opi_rep[j] . W[768:1536]  + b
// One block per span, 192 threads (6 warps), deterministic reduction:
// thread 4-term sum -> warp shuffle tree -> fixed-order 6-way cross-warp sum.
// ---------------------------------------------------------------------------
__global__ void __launch_bounds__(192) part_kernel(
    const float* __restrict__ Wv,   // (2D, 2)   row-major
    const float* __restrict__ Wc,   // (2D, 13)
    const float* __restrict__ Wp)   // (2D, 3)
{
    int s = blockIdx.x;                       // 0..511
    int rowoff = (s < NA) ? 0 : D;            // which half of W rows
    int tid = threadIdx.x;                    // 0..191

    float4 r = ((const float4*)g_rep)[(size_t)s * D4 + tid];
    int d = rowoff + tid * 4;

    float acc[NK];
    #pragma unroll
    for (int c = 0; c < 2; ++c)
        acc[c] = r.x*Wv[(d+0)*2+c] + r.y*Wv[(d+1)*2+c]
               + r.z*Wv[(d+2)*2+c] + r.w*Wv[(d+3)*2+c];
    #pragma unroll
    for (int c = 0; c < NCAT; ++c)
        acc[2+c] = r.x*Wc[(d+0)*NCAT+c] + r.y*Wc[(d+1)*NCAT+c]
                 + r.z*Wc[(d+2)*NCAT+c] + r.w*Wc[(d+3)*NCAT+c];
    #pragma unroll
    for (int c = 0; c < NPOL; ++c)
        acc[15+c] = r.x*Wp[(d+0)*NPOL+c] + r.y*Wp[(d+1)*NPOL+c]
                  + r.z*Wp[(d+2)*NPOL+c] + r.w*Wp[(d+3)*NPOL+c];

    // warp tree reduce (deterministic)
    #pragma unroll
    for (int k = 0; k < NK; ++k)
        #pragma unroll
        for (int off = 16; off > 0; off >>= 1)
            acc[k] += __shfl_xor_sync(0xFFFFFFFFu, acc[k], off);

    __shared__ float sred[6][NK];
    int warp = tid >> 5;
    if ((tid & 31) == 0) {
        #pragma unroll
        for (int k = 0; k < NK; ++k) sred[warp][k] = acc[k];
    }
    __syncthreads();
    if (tid < NK) {
        float t = 0.f;
        #pragma unroll
        for (int w = 0; w < 6; ++w) t += sred[w][tid];   // fixed order
        g_part[s * NK + tid] = t;
    }
}

// ---------------------------------------------------------------------------
// Kernel C: the 403 MB streaming write. One block per pair (65536 blocks,
// 128 threads). Reads the hot 1.5 MB rep table from L2, writes pair_reps
// with __stcs (streaming, don't evict the rep table), plus the small tails.
// ---------------------------------------------------------------------------
__global__ void __launch_bounds__(128) pair_kernel(
    const float* __restrict__ bv,
    const float* __restrict__ bc,
    const float* __restrict__ bp,
    float* __restrict__ out)
{
    int p = blockIdx.x;
    int i = p >> 8;            // aspect id
    int j = p & 255;           // opinion id

    const float* pa = g_part + i * NK;
    const float* po = g_part + (NA + j) * NK;

    float v0 = pa[0] + po[0] + bv[0];
    float v1 = pa[1] + po[1] + bv[1];
    bool m = v0 > v1;

    int t = threadIdx.x;
    const float4* ar = ((const float4*)g_rep) + (size_t)i        * D4;
    const float4* op = ((const float4*)g_rep) + (size_t)(NA + j) * D4;
    float4* outp = ((float4*)out) + (size_t)p * (2 * D4);

    const float4 z4 = make_float4(0.f, 0.f, 0.f, 0.f);
    #pragma unroll
    for (int it = 0; it < 3; ++it) {
        int c = t + it * 128;                // 0..383
        float4 v = z4;
        if (m) v = (c < D4) ? ar[c] : op[c - D4];
        __stcs(&outp[c], v);
    }

    // small tails (coalesced within a warp; tiny traffic)
    if (t < NCAT)
        out[OFF_CAT + (size_t)p * NCAT + t] = m ? (pa[2 + t] + po[2 + t] + bc[t]) : 0.f;
    if (t >= 32 && t < 32 + NPOL) {
        int k = t - 32;
        out[OFF_POL + (size_t)p * NPOL + k] = m ? (pa[15 + k] + po[15 + k] + bp[k]) : 0.f;
    }
    if (t == 64) {
        out[OFF_AID + p] = m ? (float)i : -1.f;
        out[OFF_OID + p] = m ? (float)j : -1.f;
        out[OFF_MSK + p] = m ? 1.f : 0.f;
    }
}

// ---------------------------------------------------------------------------
extern "C" void kernel_launch(void* const* d_in, const int* in_sizes, int n_in,
                              void* d_out, int out_size)
{
    const float* word_rep = (const float*)d_in[0];   // (S, D)
    const int*   aspects  = (const int*)  d_in[1];   // (NA, 2)
    const int*   opinions = (const int*)  d_in[2];   // (NO, 2)
    const float* W_valid  = (const float*)d_in[3];   // (2D, 2)
    const float* b_valid  = (const float*)d_in[4];   // (2,)
    const float* W_cat    = (const float*)d_in[5];   // (2D, 13)
    const float* b_cat    = (const float*)d_in[6];   // (13,)
    const float* W_pol    = (const float*)d_in[7];   // (2D, 3)
    const float* b_pol    = (const float*)d_in[8];   // (3,)
    float* out = (float*)d_out;

    span_pool_kernel<<<NA + NO, 192>>>(word_rep, aspects, opinions);
    part_kernel     <<<NA + NO, 192>>>(W_valid, W_cat, W_pol);
    pair_kernel     <<<NP, 128>>>(b_valid, b_cat, b_pol, out);
}